// round 9
// baseline (speedup 1.0000x reference)
#include <cuda_runtime.h>
#include <cuda_fp16.h>
#include <cstdint>

#define D        256
#define K        1024
#define HW       1024
#define NTOK     32768
#define NBLK     256
#define IDX_OFF  8388608
#define LOSS_OFF 8421376
#define MARGIN   0.12f

// gemm smem layout (bytes). 128 tokens/block, chunks of 32 codes, fp16 single.
#define OFF_A    0          // 128 x 264 halves = 67584
#define OFF_B    67584      // 2 bufs x 16896 (32 codes x 528B)
#define BBUF_SZ  16896
#define OFF_CN   101376     // 4096
#define OFF_STG  105472     // 4096 (128 tok x 2 x float4)
#define SMEM_SZ  109568

__device__ float    g_cnorm[K];
__device__ float    g_partial[NBLK];
__device__ int      g_idx[NTOK];
__device__ int      g_doubt[NTOK];
__device__ int      g_doubt_cnt;
__device__ uint16_t g_cbf16[K * D];

// ---------------- helpers ----------------
__device__ __forceinline__ uint32_t smem_u32(const void* p) {
    uint32_t a;
    asm("{ .reg .u64 t; cvta.to.shared.u64 t, %1; cvt.u32.u64 %0, t; }" : "=r"(a) : "l"(p));
    return a;
}
#define CP_ASYNC16(dst, src) \
    asm volatile("cp.async.cg.shared.global [%0], [%1], 16;" :: "r"(dst), "l"(src) : "memory")
#define CP_COMMIT() asm volatile("cp.async.commit_group;" ::: "memory")
#define CP_WAIT1()  asm volatile("cp.async.wait_group 1;" ::: "memory")
#define CP_WAIT0()  asm volatile("cp.async.wait_group 0;" ::: "memory")

__device__ __forceinline__ void ldsm_x4(uint32_t* r, uint32_t a) {
    asm volatile("ldmatrix.sync.aligned.m8n8.x4.shared.b16 {%0,%1,%2,%3}, [%4];"
        : "=r"(r[0]), "=r"(r[1]), "=r"(r[2]), "=r"(r[3]) : "r"(a));
}
__device__ __forceinline__ void mma_fp16(float* c, const uint32_t* a, const uint32_t* b) {
    asm volatile(
        "mma.sync.aligned.m16n8k16.row.col.f32.f16.f16.f32 "
        "{%0,%1,%2,%3}, {%4,%5,%6,%7}, {%8,%9}, {%0,%1,%2,%3};"
        : "+f"(c[0]), "+f"(c[1]), "+f"(c[2]), "+f"(c[3])
        : "r"(a[0]), "r"(a[1]), "r"(a[2]), "r"(a[3]), "r"(b[0]), "r"(b[1]));
}
__device__ __forceinline__ bool better(float v, int i, float V, int I) {
    return v < V || (v == V && i < I);
}

// ---------------- Kernel 0: codebook -> fp16 ----------------
__global__ void prep_kernel(const float* __restrict__ cb) {
    int i = blockIdx.x * 256 + threadIdx.x;
    g_cbf16[i] = __half_as_ushort(__float2half(cb[i]));
}

// ---------------- Kernel 1: cnorm + counter reset ----------------
__global__ void cnorm_kernel(const float* __restrict__ cb) {
    if (blockIdx.x == 0 && threadIdx.x == 0) g_doubt_cnt = 0;
    int k = blockIdx.x * 8 + (threadIdx.x >> 5);
    int lane = threadIdx.x & 31;
    const float* row = cb + k * D;
    float s = 0.f;
#pragma unroll
    for (int d = lane; d < D; d += 32) { float v = row[d]; s = fmaf(v, v, s); }
#pragma unroll
    for (int o = 16; o; o >>= 1) s += __shfl_xor_sync(~0u, s, o);
    if (lane == 0) g_cnorm[k] = s;
}

// ---------------- Kernel 2: fp16 HMMA GEMM + top-2 argmin ----------------
// 256 blocks x 128 tokens, 2 CTAs/SM (single wave). Warp tile 32x16, chunks of 32 codes.
__global__ __launch_bounds__(256, 2) void vq_gemm(const float* __restrict__ z) {
    extern __shared__ char sm[];
    const uint32_t su = smem_u32(sm);
    const int t = threadIdx.x, w = t >> 5, lane = t & 31;
    const int g = lane >> 2, p = lane & 3;
    const int mw = w >> 1, nw = w & 1;
    const int n0 = blockIdx.x * 128;
    const int b = n0 >> 10, hw0 = n0 & 1023;
    const float* zb = z + b * (D * HW) + hw0;

    uint16_t* sA  = (uint16_t*)(sm + OFF_A);
    float*    scn = (float*)(sm + OFF_CN);
    float4*   stg = (float4*)(sm + OFF_STG);

    // ---- A: load z coalesced (128 tokens x 256 dims) -> fp16 smem [tok][dim] ----
#pragma unroll
    for (int j = 0; j < 32; j++) {
        int l = j * 256 + t;
        int d = l >> 5, f4 = l & 31;
        float4 v = *(const float4*)(zb + d * HW + f4 * 4);
        float vv[4] = {v.x, v.y, v.z, v.w};
#pragma unroll
        for (int q = 0; q < 4; q++)
            sA[(f4 * 4 + q) * 264 + d] = __half_as_ushort(__float2half(vv[q]));
    }
    for (int c = t; c < K; c += 256) scn[c] = g_cnorm[c];

    // prefetch B chunk 0: 32 codes x 512B = 1024 cp16, 4 per thread
#pragma unroll
    for (int j = 0; j < 4; j++) {
        int s = j * 256 + t;
        int code = s >> 5, seg = s & 31;
        uint32_t dst = su + OFF_B + code * 528 + seg * 16;
        CP_ASYNC16(dst, (const char*)g_cbf16 + code * 512 + seg * 16);
    }
    CP_COMMIT();
    __syncthreads();

    // ldmatrix lane addresses
    const int l8 = lane & 7, mat = lane >> 3;
    const uint32_t aAddr = su + OFF_A
        + (uint32_t)((mw * 32 + l8 + (mat & 1) * 8) * 528 + (mat >> 1) * 16);
    const uint32_t boff = (uint32_t)((nw * 16 + (mat >> 1) * 8 + l8) * 528 + (mat & 1) * 16);

    float rv1[2][2], rv2[2][2];
    int   ri1[2][2], ri2[2][2];
#pragma unroll
    for (int mt = 0; mt < 2; mt++)
#pragma unroll
        for (int rr = 0; rr < 2; rr++) {
            rv1[mt][rr] = 3.4e38f; rv2[mt][rr] = 3.4e38f;
            ri1[mt][rr] = 0; ri2[mt][rr] = 0;
        }

    for (int nc = 0; nc < 32; nc++) {
        if (nc < 31) {
            int nn = nc + 1, buf = nn & 1;
#pragma unroll
            for (int j = 0; j < 4; j++) {
                int s = j * 256 + t;
                int code = s >> 5, seg = s & 31;
                uint32_t dst = su + OFF_B + buf * BBUF_SZ + code * 528 + seg * 16;
                CP_ASYNC16(dst, (const char*)g_cbf16 + (nn * 32 + code) * 512 + seg * 16);
            }
            CP_COMMIT();
            CP_WAIT1();
        } else {
            CP_WAIT0();
        }
        __syncthreads();

        const uint32_t bAddr = su + OFF_B + (uint32_t)(nc & 1) * BBUF_SZ + boff;

        float acc[2][2][4];
#pragma unroll
        for (int mt = 0; mt < 2; mt++)
#pragma unroll
            for (int nt = 0; nt < 2; nt++)
#pragma unroll
                for (int q = 0; q < 4; q++) acc[mt][nt][q] = 0.f;

        // fragment double-buffer across ks
        uint32_t ah[2][2][4], bb[2][4];
        ldsm_x4(ah[0][0], aAddr);
        ldsm_x4(ah[0][1], aAddr + 16 * 528);
        ldsm_x4(bb[0], bAddr);

#pragma unroll
        for (int ks = 0; ks < 16; ks++) {
            const int cur = ks & 1, nxt = cur ^ 1;
            if (ks < 15) {
                uint32_t ko = (uint32_t)((ks + 1) * 32);
                ldsm_x4(ah[nxt][0], aAddr + ko);
                ldsm_x4(ah[nxt][1], aAddr + 16 * 528 + ko);
                ldsm_x4(bb[nxt], bAddr + ko);
            }
#pragma unroll
            for (int mt = 0; mt < 2; mt++)
#pragma unroll
                for (int nt = 0; nt < 2; nt++)
                    mma_fp16(acc[mt][nt], ah[cur][mt], &bb[cur][nt * 2]);
        }

        // fold into running top-2 (codes ascending per thread)
#pragma unroll
        for (int nt = 0; nt < 2; nt++)
#pragma unroll
            for (int q = 0; q < 2; q++) {
                int c = nc * 32 + nw * 16 + nt * 8 + 2 * p + q;
                float cn = scn[c];
#pragma unroll
                for (int mt = 0; mt < 2; mt++)
#pragma unroll
                    for (int rr = 0; rr < 2; rr++) {
                        float v = fmaf(-2.f, acc[mt][nt][rr * 2 + q], cn);
                        if (v < rv1[mt][rr]) {
                            rv2[mt][rr] = rv1[mt][rr]; ri2[mt][rr] = ri1[mt][rr];
                            rv1[mt][rr] = v;           ri1[mt][rr] = c;
                        } else if (v < rv2[mt][rr]) {
                            rv2[mt][rr] = v;           ri2[mt][rr] = c;
                        }
                    }
            }
        __syncthreads();
    }

    // ---- merge top-2 across p lanes (xor 1, 2) ----
#pragma unroll
    for (int o = 1; o <= 2; o <<= 1) {
#pragma unroll
        for (int mt = 0; mt < 2; mt++)
#pragma unroll
            for (int rr = 0; rr < 2; rr++) {
                float ov1 = __shfl_xor_sync(~0u, rv1[mt][rr], o);
                int   oi1 = __shfl_xor_sync(~0u, ri1[mt][rr], o);
                float ov2 = __shfl_xor_sync(~0u, rv2[mt][rr], o);
                int   oi2 = __shfl_xor_sync(~0u, ri2[mt][rr], o);
                if (better(ov1, oi1, rv1[mt][rr], ri1[mt][rr])) {
                    if (better(rv1[mt][rr], ri1[mt][rr], ov2, oi2)) {
                        rv2[mt][rr] = rv1[mt][rr]; ri2[mt][rr] = ri1[mt][rr];
                    } else { rv2[mt][rr] = ov2; ri2[mt][rr] = oi2; }
                    rv1[mt][rr] = ov1; ri1[mt][rr] = oi1;
                } else if (better(ov1, oi1, rv2[mt][rr], ri2[mt][rr])) {
                    rv2[mt][rr] = ov1; ri2[mt][rr] = oi1;
                }
            }
    }
    if (p == 0) {
#pragma unroll
        for (int mt = 0; mt < 2; mt++)
#pragma unroll
            for (int rr = 0; rr < 2; rr++) {
                int tok = mw * 32 + mt * 16 + rr * 8 + g;
                stg[tok * 2 + nw] = make_float4(rv1[mt][rr], __int_as_float(ri1[mt][rr]),
                                                rv2[mt][rr], __int_as_float(ri2[mt][rr]));
            }
    }
    __syncthreads();

    if (t < 128) {
        float4 a = stg[t * 2], bq = stg[t * 2 + 1];
        float v1 = a.x, v2 = a.z; int i1 = __float_as_int(a.y), i2 = __float_as_int(a.w);
        float w1 = bq.x, w2 = bq.z; int j1 = __float_as_int(bq.y), j2 = __float_as_int(bq.w);
        float fv1, fv2; int fi1;
        if (better(w1, j1, v1, i1)) {
            fv1 = w1; fi1 = j1;
            fv2 = better(v1, i1, w2, j2) ? v1 : w2;
        } else {
            fv1 = v1; fi1 = i1;
            fv2 = better(w1, j1, v2, i2) ? w1 : v2;
        }
        g_idx[n0 + t] = fi1;
        if (fv2 - fv1 < MARGIN) {
            int s = atomicAdd(&g_doubt_cnt, 1);
            g_doubt[s] = n0 + t;
        }
    }
}

// ---------------- Kernel 3: exact fp32 full-scan rescue ----------------
// 256 blocks x 8 warps; one token per WARP, z in smem (broadcast reads),
// each lane owns codes == lane (mod 32) with 4 concurrent 256-deep FMA chains.
__global__ __launch_bounds__(256) void rescue_kernel(const float* __restrict__ z,
                                                     const float* __restrict__ cb) {
    __shared__ float sz[8][264];
    const int t = threadIdx.x, w = t >> 5, lane = t & 31;
    const int cnt = g_doubt_cnt;
    for (int e0 = blockIdx.x * 8; e0 < cnt; e0 += gridDim.x * 8) {
        const int e = e0 + w;
        const bool active = e < cnt;
        const int n = g_doubt[active ? e : e0];
        {   // load this warp's token into its smem row
            int bb = n >> 10, hw = n & 1023;
            const float* zp = z + bb * (D * HW) + hw;
#pragma unroll
            for (int d = lane; d < D; d += 32) sz[w][d] = zp[d * HW];
        }
        __syncwarp();

        float bv = 3.4e38f; int bi = 0;
        const float4* szp = (const float4*)sz[w];
#pragma unroll 1
        for (int grp = 0; grp < 8; grp++) {
            int c0 = grp * 128 + lane;         // codes c0, c0+32, c0+64, c0+96
            const float4* r0 = (const float4*)(cb + (c0)      * D);
            const float4* r1 = (const float4*)(cb + (c0 + 32) * D);
            const float4* r2 = (const float4*)(cb + (c0 + 64) * D);
            const float4* r3 = (const float4*)(cb + (c0 + 96) * D);
            float d0 = 0.f, d1 = 0.f, d2 = 0.f, d3 = 0.f;
#pragma unroll 8
            for (int q = 0; q < 64; q++) {
                float4 zv = szp[q];
                float4 a = __ldg(r0 + q), bq = __ldg(r1 + q);
                float4 cq = __ldg(r2 + q), dq = __ldg(r3 + q);
                d0 = fmaf(zv.x, a.x,  d0); d1 = fmaf(zv.x, bq.x, d1);
                d2 = fmaf(zv.x, cq.x, d2); d3 = fmaf(zv.x, dq.x, d3);
                d0 = fmaf(zv.y, a.y,  d0); d1 = fmaf(zv.y, bq.y, d1);
                d2 = fmaf(zv.y, cq.y, d2); d3 = fmaf(zv.y, dq.y, d3);
                d0 = fmaf(zv.z, a.z,  d0); d1 = fmaf(zv.z, bq.z, d1);
                d2 = fmaf(zv.z, cq.z, d2); d3 = fmaf(zv.z, dq.z, d3);
                d0 = fmaf(zv.w, a.w,  d0); d1 = fmaf(zv.w, bq.w, d1);
                d2 = fmaf(zv.w, cq.w, d2); d3 = fmaf(zv.w, dq.w, d3);
            }
            float vv0 = fmaf(-2.f, d0, g_cnorm[c0]);
            float vv1 = fmaf(-2.f, d1, g_cnorm[c0 + 32]);
            float vv2 = fmaf(-2.f, d2, g_cnorm[c0 + 64]);
            float vv3 = fmaf(-2.f, d3, g_cnorm[c0 + 96]);
            if (vv0 < bv) { bv = vv0; bi = c0; }        // ascending per lane
            if (vv1 < bv) { bv = vv1; bi = c0 + 32; }
            if (vv2 < bv) { bv = vv2; bi = c0 + 64; }
            if (vv3 < bv) { bv = vv3; bi = c0 + 96; }
        }
        // cross-lane merge (index tie-break -> first-min)
#pragma unroll
        for (int o = 16; o; o >>= 1) {
            float ov = __shfl_xor_sync(~0u, bv, o);
            int   oi = __shfl_xor_sync(~0u, bi, o);
            if (ov < bv || (ov == bv && oi < bi)) { bv = ov; bi = oi; }
        }
        if (active && lane == 0) g_idx[n] = bi;
        __syncwarp();
    }
}

// ---------------- Kernel 4: outputs ----------------
__global__ __launch_bounds__(256) void vq_out(const float* __restrict__ z,
                                              const float* __restrict__ cb,
                                              float* __restrict__ out) {
    __shared__ int rowIdx[128];
    __shared__ float wsum[8];
    const int t = threadIdx.x;
    const int n0 = blockIdx.x * 128;
    const int b = n0 >> 10, hw0 = n0 & 1023;
    if (t < 128) {
        int idx = g_idx[n0 + t];
        rowIdx[t] = idx;
        out[IDX_OFF + n0 + t] = (float)idx;
    }
    __syncthreads();
    const float* zb = z + b * (D * HW) + hw0;
    float* outz = out + b * (D * HW) + hw0;
    float lsum = 0.f;
#pragma unroll 4
    for (int j = 0; j < 128; j++) {
        int l = j * 256 + t;
        int i = l & 127, d = l >> 7;
        float ze = zb[d * HW + i];
        float zq = __ldg(cb + rowIdx[i] * D + d);
        float diff = zq - ze;
        outz[d * HW + i] = ze + diff;
        lsum = fmaf(diff, diff, lsum);
    }
#pragma unroll
    for (int o = 16; o; o >>= 1) lsum += __shfl_xor_sync(~0u, lsum, o);
    if ((t & 31) == 0) wsum[t >> 5] = lsum;
    __syncthreads();
    if (t == 0) {
        float s = 0.f;
#pragma unroll
        for (int ww = 0; ww < 8; ww++) s += wsum[ww];
        g_partial[blockIdx.x] = s;
    }
}

__global__ void finalize_kernel(float* __restrict__ out) {
    float s = 0.f;
    for (int i = 0; i < NBLK; i++) s += g_partial[i];
    float mean = s / 8388608.f;
    out[LOSS_OFF] = mean + 0.25f * mean;
}

// ---------------------------------------------------------------------------
extern "C" void kernel_launch(void* const* d_in, const int* in_sizes, int n_in,
                              void* d_out, int out_size) {
    const float* z  = (const float*)d_in[0];
    const float* cb = (const float*)d_in[1];
    float* out = (float*)d_out;

    cudaFuncSetAttribute(vq_gemm, cudaFuncAttributeMaxDynamicSharedMemorySize, SMEM_SZ);

    prep_kernel<<<1024, 256>>>(cb);
    cnorm_kernel<<<128, 256>>>(cb);
    vq_gemm<<<NBLK, 256, SMEM_SZ>>>(z);
    rescue_kernel<<<256, 256>>>(z, cb);
    vq_out<<<NBLK, 256>>>(z, cb, out);
    finalize_kernel<<<1, 1>>>(out);
}

// round 10
// speedup vs baseline: 1.7825x; 1.7825x over previous
#include <cuda_runtime.h>
#include <cuda_fp16.h>
#include <cstdint>

#define D        256
#define K        1024
#define HW       1024
#define NTOK     32768
#define NBLK     256
#define IDX_OFF  8388608
#define LOSS_OFF 8421376
#define MARGIN   0.12f

// gemm smem layout (bytes). 128 tokens/block, chunks of 32 codes, fp16.
#define OFF_A    0          // 128 x 264 halves = 67584
#define OFF_B    67584      // 2 bufs x 16896 (32 codes x 528B)
#define BBUF_SZ  16896
#define OFF_CN   101376     // 4096
#define OFF_STG  105472     // 8192 (128 tok x 2 nw x 2 float4)
#define SMEM_SZ  113664

__device__ float    g_cnorm[K];
__device__ float    g_partial[NBLK];
__device__ int      g_idx[NTOK];
__device__ int4     g_pair[NTOK];
__device__ int      g_pair_cnt;
__device__ int      g_deep[NTOK];
__device__ int      g_deep_cnt;
__device__ uint16_t g_cbf16[K * D];

// ---------------- helpers ----------------
__device__ __forceinline__ uint32_t smem_u32(const void* p) {
    uint32_t a;
    asm("{ .reg .u64 t; cvta.to.shared.u64 t, %1; cvt.u32.u64 %0, t; }" : "=r"(a) : "l"(p));
    return a;
}
#define CP_ASYNC16(dst, src) \
    asm volatile("cp.async.cg.shared.global [%0], [%1], 16;" :: "r"(dst), "l"(src) : "memory")
#define CP_COMMIT() asm volatile("cp.async.commit_group;" ::: "memory")
#define CP_WAIT1()  asm volatile("cp.async.wait_group 1;" ::: "memory")
#define CP_WAIT0()  asm volatile("cp.async.wait_group 0;" ::: "memory")

__device__ __forceinline__ void ldsm_x4(uint32_t* r, uint32_t a) {
    asm volatile("ldmatrix.sync.aligned.m8n8.x4.shared.b16 {%0,%1,%2,%3}, [%4];"
        : "=r"(r[0]), "=r"(r[1]), "=r"(r[2]), "=r"(r[3]) : "r"(a));
}
__device__ __forceinline__ void mma_fp16(float* c, const uint32_t* a, const uint32_t* b) {
    asm volatile(
        "mma.sync.aligned.m16n8k16.row.col.f32.f16.f16.f32 "
        "{%0,%1,%2,%3}, {%4,%5,%6,%7}, {%8,%9}, {%0,%1,%2,%3};"
        : "+f"(c[0]), "+f"(c[1]), "+f"(c[2]), "+f"(c[3])
        : "r"(a[0]), "r"(a[1]), "r"(a[2]), "r"(a[3]), "r"(b[0]), "r"(b[1]));
}
__device__ __forceinline__ bool better(float v, int i, float V, int I) {
    return v < V || (v == V && i < I);
}
// insert (v,i) into sorted top-3 (stable: ties keep smaller index via better())
__device__ __forceinline__ void ins3(float v, int i,
                                     float& v1, int& i1, float& v2, int& i2,
                                     float& v3, int& i3) {
    if (better(v, i, v1, i1))      { v3 = v2; i3 = i2; v2 = v1; i2 = i1; v1 = v; i1 = i; }
    else if (better(v, i, v2, i2)) { v3 = v2; i3 = i2; v2 = v;  i2 = i; }
    else if (better(v, i, v3, i3)) { v3 = v;  i3 = i; }
}
// order-preserving float->uint key
__device__ __forceinline__ uint32_t fkey(float f) {
    uint32_t u = __float_as_uint(f);
    return (u & 0x80000000u) ? ~u : (u | 0x80000000u);
}

// ---------------- Kernel 0: codebook -> fp16 ----------------
__global__ void prep_kernel(const float* __restrict__ cb) {
    int i = blockIdx.x * 256 + threadIdx.x;
    g_cbf16[i] = __half_as_ushort(__float2half(cb[i]));
}

// ---------------- Kernel 1: cnorm + counter reset ----------------
__global__ void cnorm_kernel(const float* __restrict__ cb) {
    if (blockIdx.x == 0 && threadIdx.x == 0) { g_pair_cnt = 0; g_deep_cnt = 0; }
    int k = blockIdx.x * 8 + (threadIdx.x >> 5);
    int lane = threadIdx.x & 31;
    const float* row = cb + k * D;
    float s = 0.f;
#pragma unroll
    for (int d = lane; d < D; d += 32) { float v = row[d]; s = fmaf(v, v, s); }
#pragma unroll
    for (int o = 16; o; o >>= 1) s += __shfl_xor_sync(~0u, s, o);
    if (lane == 0) g_cnorm[k] = s;
}

// ---------------- Kernel 2: fp16 HMMA GEMM + top-3 argmin ----------------
__global__ __launch_bounds__(256, 2) void vq_gemm(const float* __restrict__ z) {
    extern __shared__ char sm[];
    const uint32_t su = smem_u32(sm);
    const int t = threadIdx.x, w = t >> 5, lane = t & 31;
    const int g = lane >> 2, p = lane & 3;
    const int mw = w >> 1, nw = w & 1;
    const int n0 = blockIdx.x * 128;
    const int b = n0 >> 10, hw0 = n0 & 1023;
    const float* zb = z + b * (D * HW) + hw0;

    uint16_t* sA  = (uint16_t*)(sm + OFF_A);
    float*    scn = (float*)(sm + OFF_CN);
    float4*   stg = (float4*)(sm + OFF_STG);

    // ---- A: load z coalesced -> fp16 smem [tok][dim] ----
#pragma unroll
    for (int j = 0; j < 32; j++) {
        int l = j * 256 + t;
        int d = l >> 5, f4 = l & 31;
        float4 v = *(const float4*)(zb + d * HW + f4 * 4);
        float vv[4] = {v.x, v.y, v.z, v.w};
#pragma unroll
        for (int q = 0; q < 4; q++)
            sA[(f4 * 4 + q) * 264 + d] = __half_as_ushort(__float2half(vv[q]));
    }
    for (int c = t; c < K; c += 256) scn[c] = g_cnorm[c];

#pragma unroll
    for (int j = 0; j < 4; j++) {
        int s = j * 256 + t;
        int code = s >> 5, seg = s & 31;
        CP_ASYNC16(su + OFF_B + code * 528 + seg * 16,
                   (const char*)g_cbf16 + code * 512 + seg * 16);
    }
    CP_COMMIT();
    __syncthreads();

    const int l8 = lane & 7, mat = lane >> 3;
    const uint32_t aAddr = su + OFF_A
        + (uint32_t)((mw * 32 + l8 + (mat & 1) * 8) * 528 + (mat >> 1) * 16);
    const uint32_t boff = (uint32_t)((nw * 16 + (mat >> 1) * 8 + l8) * 528 + (mat & 1) * 16);

    float rv1[2][2], rv2[2][2], rv3[2][2];
    int   ri1[2][2], ri2[2][2], ri3[2][2];
#pragma unroll
    for (int mt = 0; mt < 2; mt++)
#pragma unroll
        for (int rr = 0; rr < 2; rr++) {
            rv1[mt][rr] = 3.4e38f; rv2[mt][rr] = 3.4e38f; rv3[mt][rr] = 3.4e38f;
            ri1[mt][rr] = 0; ri2[mt][rr] = 0; ri3[mt][rr] = 0;
        }

    for (int nc = 0; nc < 32; nc++) {
        if (nc < 31) {
            int nn = nc + 1, buf = nn & 1;
#pragma unroll
            for (int j = 0; j < 4; j++) {
                int s = j * 256 + t;
                int code = s >> 5, seg = s & 31;
                CP_ASYNC16(su + OFF_B + buf * BBUF_SZ + code * 528 + seg * 16,
                           (const char*)g_cbf16 + (nn * 32 + code) * 512 + seg * 16);
            }
            CP_COMMIT();
            CP_WAIT1();
        } else {
            CP_WAIT0();
        }
        __syncthreads();

        const uint32_t bAddr = su + OFF_B + (uint32_t)(nc & 1) * BBUF_SZ + boff;

        float acc[2][2][4];
#pragma unroll
        for (int mt = 0; mt < 2; mt++)
#pragma unroll
            for (int nt = 0; nt < 2; nt++)
#pragma unroll
                for (int q = 0; q < 4; q++) acc[mt][nt][q] = 0.f;

        uint32_t ah[2][2][4], bb[2][4];
        ldsm_x4(ah[0][0], aAddr);
        ldsm_x4(ah[0][1], aAddr + 16 * 528);
        ldsm_x4(bb[0], bAddr);

#pragma unroll
        for (int ks = 0; ks < 16; ks++) {
            const int cur = ks & 1, nxt = cur ^ 1;
            if (ks < 15) {
                uint32_t ko = (uint32_t)((ks + 1) * 32);
                ldsm_x4(ah[nxt][0], aAddr + ko);
                ldsm_x4(ah[nxt][1], aAddr + 16 * 528 + ko);
                ldsm_x4(bb[nxt], bAddr + ko);
            }
#pragma unroll
            for (int mt = 0; mt < 2; mt++)
#pragma unroll
                for (int nt = 0; nt < 2; nt++)
                    mma_fp16(acc[mt][nt], ah[cur][mt], &bb[cur][nt * 2]);
        }

        // fold into running top-3 (codes ascending per thread)
#pragma unroll
        for (int nt = 0; nt < 2; nt++)
#pragma unroll
            for (int q = 0; q < 2; q++) {
                int c = nc * 32 + nw * 16 + nt * 8 + 2 * p + q;
                float cn = scn[c];
#pragma unroll
                for (int mt = 0; mt < 2; mt++)
#pragma unroll
                    for (int rr = 0; rr < 2; rr++) {
                        float v = fmaf(-2.f, acc[mt][nt][rr * 2 + q], cn);
                        ins3(v, c, rv1[mt][rr], ri1[mt][rr], rv2[mt][rr], ri2[mt][rr],
                             rv3[mt][rr], ri3[mt][rr]);
                    }
            }
        __syncthreads();
    }

    // ---- merge top-3 across p lanes (xor 1, 2) ----
#pragma unroll
    for (int o = 1; o <= 2; o <<= 1) {
#pragma unroll
        for (int mt = 0; mt < 2; mt++)
#pragma unroll
            for (int rr = 0; rr < 2; rr++) {
                float ov1 = __shfl_xor_sync(~0u, rv1[mt][rr], o);
                int   oi1 = __shfl_xor_sync(~0u, ri1[mt][rr], o);
                float ov2 = __shfl_xor_sync(~0u, rv2[mt][rr], o);
                int   oi2 = __shfl_xor_sync(~0u, ri2[mt][rr], o);
                float ov3 = __shfl_xor_sync(~0u, rv3[mt][rr], o);
                int   oi3 = __shfl_xor_sync(~0u, ri3[mt][rr], o);
                ins3(ov1, oi1, rv1[mt][rr], ri1[mt][rr], rv2[mt][rr], ri2[mt][rr],
                     rv3[mt][rr], ri3[mt][rr]);
                ins3(ov2, oi2, rv1[mt][rr], ri1[mt][rr], rv2[mt][rr], ri2[mt][rr],
                     rv3[mt][rr], ri3[mt][rr]);
                ins3(ov3, oi3, rv1[mt][rr], ri1[mt][rr], rv2[mt][rr], ri2[mt][rr],
                     rv3[mt][rr], ri3[mt][rr]);
            }
    }
    if (p == 0) {
#pragma unroll
        for (int mt = 0; mt < 2; mt++)
#pragma unroll
            for (int rr = 0; rr < 2; rr++) {
                int tok = mw * 32 + mt * 16 + rr * 8 + g;
                stg[(tok * 2 + nw) * 2 + 0] =
                    make_float4(rv1[mt][rr], __int_as_float(ri1[mt][rr]),
                                rv2[mt][rr], __int_as_float(ri2[mt][rr]));
                stg[(tok * 2 + nw) * 2 + 1] =
                    make_float4(rv3[mt][rr], __int_as_float(ri3[mt][rr]), 0.f, 0.f);
            }
    }
    __syncthreads();

    if (t < 128) {
        float4 a0 = stg[(t * 2 + 0) * 2], a1 = stg[(t * 2 + 0) * 2 + 1];
        float4 b0 = stg[(t * 2 + 1) * 2], b1 = stg[(t * 2 + 1) * 2 + 1];
        float fv1 = a0.x, fv2 = a0.z, fv3 = a1.x;
        int   fi1 = __float_as_int(a0.y), fi2 = __float_as_int(a0.w),
              fi3 = __float_as_int(a1.y);
        ins3(b0.x, __float_as_int(b0.y), fv1, fi1, fv2, fi2, fv3, fi3);
        ins3(b0.z, __float_as_int(b0.w), fv1, fi1, fv2, fi2, fv3, fi3);
        ins3(b1.x, __float_as_int(b1.y), fv1, fi1, fv2, fi2, fv3, fi3);
        g_idx[n0 + t] = fi1;
        if (fv3 - fv1 < MARGIN) {
            int s = atomicAdd(&g_deep_cnt, 1);
            g_deep[s] = n0 + t;
        } else if (fv2 - fv1 < MARGIN) {
            int s = atomicAdd(&g_pair_cnt, 1);
            g_pair[s] = make_int4(n0 + t, fi1, fi2, 0);
        }
    }
}

// ---------------- Kernel 3a: exact fp32 pair rescore (one warp/token) ----------------
__global__ __launch_bounds__(256) void pair_kernel(const float* __restrict__ z,
                                                   const float* __restrict__ cb) {
    int wid = (blockIdx.x * blockDim.x + threadIdx.x) >> 5;
    int lane = threadIdx.x & 31;
    int stride = (gridDim.x * blockDim.x) >> 5;
    int cnt = g_pair_cnt;
    for (int i = wid; i < cnt; i += stride) {
        int4 pq = g_pair[i];
        int n = pq.x, c1 = pq.y, c2 = pq.z;
        int bb = n >> 10, hw = n & 1023;
        const float* zp = z + bb * (D * HW) + hw;
        const float* p1 = cb + c1 * D;
        const float* p2 = cb + c2 * D;
        float zz = 0.f, d1 = 0.f, d2 = 0.f;
#pragma unroll
        for (int d = lane; d < D; d += 32) {
            float ze = zp[d * HW];
            zz = fmaf(ze, ze, zz);
            d1 = fmaf(ze, __ldg(p1 + d), d1);
            d2 = fmaf(ze, __ldg(p2 + d), d2);
        }
#pragma unroll
        for (int o = 16; o; o >>= 1) {
            zz += __shfl_xor_sync(~0u, zz, o);
            d1 += __shfl_xor_sync(~0u, d1, o);
            d2 += __shfl_xor_sync(~0u, d2, o);
        }
        if (lane == 0) {
            float D1 = __fadd_rn(__fsub_rn(zz, __fmul_rn(2.f, d1)), g_cnorm[c1]);
            float D2 = __fadd_rn(__fsub_rn(zz, __fmul_rn(2.f, d2)), g_cnorm[c2]);
            g_idx[n] = better(D2, c2, D1, c1) ? c2 : c1;
        }
    }
}

// ---------------- Kernel 3b: exact fp32 full scan for deep-doubt (rare) ----------------
__global__ __launch_bounds__(256) void deep_kernel(const float* __restrict__ z,
                                                   const float* __restrict__ cb) {
    __shared__ float sz[D];
    __shared__ unsigned long long sbest;
    const int t = threadIdx.x;
    const int cnt = g_deep_cnt;
    for (int e = blockIdx.x; e < cnt; e += gridDim.x) {
        int n = g_deep[e];
        int bb = n >> 10, hw = n & 1023;
        sz[t] = z[bb * (D * HW) + t * HW + hw];
        if (t == 0) sbest = ~0ull;
        __syncthreads();
        float bv = 3.4e38f; int bi = 0;
        const float4* szp = (const float4*)sz;
#pragma unroll
        for (int j = 0; j < 4; j++) {
            int c = t + j * 256;                       // ascending per thread
            const float4* row = (const float4*)(cb + c * D);
            float dsum = 0.f;
#pragma unroll 8
            for (int q = 0; q < 64; q++) {
                float4 zv = szp[q];
                float4 rv = __ldg(row + q);
                dsum = fmaf(zv.x, rv.x, dsum);
                dsum = fmaf(zv.y, rv.y, dsum);
                dsum = fmaf(zv.z, rv.z, dsum);
                dsum = fmaf(zv.w, rv.w, dsum);
            }
            float v = fmaf(-2.f, dsum, g_cnorm[c]);
            if (v < bv) { bv = v; bi = c; }
        }
        unsigned long long key = ((unsigned long long)fkey(bv) << 32) | (uint32_t)bi;
        atomicMin(&sbest, key);
        __syncthreads();
        if (t == 0) g_idx[n] = (int)(sbest & 0xffffffffu);
        __syncthreads();
    }
}

// ---------------- Kernel 4: outputs ----------------
__global__ __launch_bounds__(256) void vq_out(const float* __restrict__ z,
                                              const float* __restrict__ cb,
                                              float* __restrict__ out) {
    __shared__ int rowIdx[128];
    __shared__ float wsum[8];
    const int t = threadIdx.x;
    const int n0 = blockIdx.x * 128;
    const int b = n0 >> 10, hw0 = n0 & 1023;
    if (t < 128) {
        int idx = g_idx[n0 + t];
        rowIdx[t] = idx;
        out[IDX_OFF + n0 + t] = (float)idx;
    }
    __syncthreads();
    const float* zb = z + b * (D * HW) + hw0;
    float* outz = out + b * (D * HW) + hw0;
    float lsum = 0.f;
#pragma unroll 4
    for (int j = 0; j < 128; j++) {
        int l = j * 256 + t;
        int i = l & 127, d = l >> 7;
        float ze = zb[d * HW + i];
        float zq = __ldg(cb + rowIdx[i] * D + d);
        float diff = zq - ze;
        outz[d * HW + i] = ze + diff;
        lsum = fmaf(diff, diff, lsum);
    }
#pragma unroll
    for (int o = 16; o; o >>= 1) lsum += __shfl_xor_sync(~0u, lsum, o);
    if ((t & 31) == 0) wsum[t >> 5] = lsum;
    __syncthreads();
    if (t == 0) {
        float s = 0.f;
#pragma unroll
        for (int ww = 0; ww < 8; ww++) s += wsum[ww];
        g_partial[blockIdx.x] = s;
    }
}

__global__ void finalize_kernel(float* __restrict__ out) {
    float s = 0.f;
    for (int i = 0; i < NBLK; i++) s += g_partial[i];
    float mean = s / 8388608.f;
    out[LOSS_OFF] = mean + 0.25f * mean;
}

// ---------------------------------------------------------------------------
extern "C" void kernel_launch(void* const* d_in, const int* in_sizes, int n_in,
                              void* d_out, int out_size) {
    const float* z  = (const float*)d_in[0];
    const float* cb = (const float*)d_in[1];
    float* out = (float*)d_out;

    cudaFuncSetAttribute(vq_gemm, cudaFuncAttributeMaxDynamicSharedMemorySize, SMEM_SZ);

    prep_kernel<<<1024, 256>>>(cb);
    cnorm_kernel<<<128, 256>>>(cb);
    vq_gemm<<<NBLK, 256, SMEM_SZ>>>(z);
    pair_kernel<<<64, 256>>>(z, cb);
    deep_kernel<<<64, 256>>>(z, cb);
    vq_out<<<NBLK, 256>>>(z, cb, out);
    finalize_kernel<<<1, 1>>>(out);
}

// round 11
// speedup vs baseline: 2.3350x; 1.3100x over previous
#include <cuda_runtime.h>
#include <cuda_fp16.h>
#include <cstdint>

#define D        256
#define K        1024
#define HW       1024
#define NBLK     256
#define IDX_OFF  8388608
#define LOSS_OFF 8421376
#define MARGIN   0.12f

// smem layout (bytes)
#define OFF_A    0          // 128 x 264 halves = 67584
#define OFF_B    67584      // 2 bufs x 16896 (32 codes x 528B); reused as sz later
#define BBUF_SZ  16896
#define OFF_CN   101376     // 4096
#define OFF_STG  105472     // 256 x float4 = 4096
#define OFF_V3   109568     // 256 x float = 1024
#define OFF_ROW  110592     // 128 x int = 512
#define OFF_PT   111104     // pair tok, 128 x int
#define OFF_PC   111616     // pair codes, 128 x int2 = 1024
#define OFF_DP   112640     // deep tok, 128 x int
#define OFF_CNT  113152     // [0] pairCnt, [1] deepCnt; sbest @ +8; wsum @ +16
#define SMEM_SZ  113280

__device__ float    g_cnorm[K];
__device__ float    g_partial[NBLK];
__device__ uint16_t g_cbf16[K * D];

// ---------------- helpers ----------------
__device__ __forceinline__ uint32_t smem_u32(const void* p) {
    uint32_t a;
    asm("{ .reg .u64 t; cvta.to.shared.u64 t, %1; cvt.u32.u64 %0, t; }" : "=r"(a) : "l"(p));
    return a;
}
#define CP_ASYNC16(dst, src) \
    asm volatile("cp.async.cg.shared.global [%0], [%1], 16;" :: "r"(dst), "l"(src) : "memory")
#define CP_COMMIT() asm volatile("cp.async.commit_group;" ::: "memory")
#define CP_WAIT1()  asm volatile("cp.async.wait_group 1;" ::: "memory")
#define CP_WAIT0()  asm volatile("cp.async.wait_group 0;" ::: "memory")

__device__ __forceinline__ void ldsm_x4(uint32_t* r, uint32_t a) {
    asm volatile("ldmatrix.sync.aligned.m8n8.x4.shared.b16 {%0,%1,%2,%3}, [%4];"
        : "=r"(r[0]), "=r"(r[1]), "=r"(r[2]), "=r"(r[3]) : "r"(a));
}
__device__ __forceinline__ void mma_fp16(float* c, const uint32_t* a, const uint32_t* b) {
    asm volatile(
        "mma.sync.aligned.m16n8k16.row.col.f32.f16.f16.f32 "
        "{%0,%1,%2,%3}, {%4,%5,%6,%7}, {%8,%9}, {%0,%1,%2,%3};"
        : "+f"(c[0]), "+f"(c[1]), "+f"(c[2]), "+f"(c[3])
        : "r"(a[0]), "r"(a[1]), "r"(a[2]), "r"(a[3]), "r"(b[0]), "r"(b[1]));
}
__device__ __forceinline__ bool better(float v, int i, float V, int I) {
    return v < V || (v == V && i < I);
}
// branchless insert into (v1,i1) <= (v2,i2), v3 = 3rd-smallest value
__device__ __forceinline__ void ins2v3(float v, int i,
                                       float& v1, int& i1, float& v2, int& i2, float& v3) {
    bool lt2 = better(v, i, v2, i2);
    bool lt1 = better(v, i, v1, i1);
    v3 = lt2 ? v2 : fminf(v3, v);
    float nv2 = lt1 ? v1 : v;  int ni2 = lt1 ? i1 : i;
    v2 = lt2 ? nv2 : v2;       i2 = lt2 ? ni2 : i2;
    v1 = lt1 ? v : v1;         i1 = lt1 ? i : i1;
}
__device__ __forceinline__ uint32_t fkey(float f) {
    uint32_t u = __float_as_uint(f);
    return (u & 0x80000000u) ? ~u : (u | 0x80000000u);
}

// ---------------- Kernel 0: codebook -> fp16 + cnorm (fused) ----------------
__global__ __launch_bounds__(256) void prepcn_kernel(const float* __restrict__ cb) {
    __shared__ float ws[8];
    const int r = blockIdx.x, t = threadIdx.x;
    float v = cb[r * D + t];
    g_cbf16[r * D + t] = __half_as_ushort(__float2half(v));
    float s = v * v;
#pragma unroll
    for (int o = 16; o; o >>= 1) s += __shfl_xor_sync(~0u, s, o);
    if ((t & 31) == 0) ws[t >> 5] = s;
    __syncthreads();
    if (t == 0) {
        float tot = 0.f;
#pragma unroll
        for (int i = 0; i < 8; i++) tot += ws[i];
        g_cnorm[r] = tot;
    }
}

// ---------------- Kernel 1: fused GEMM + argmin + rescue + outputs ----------------
__global__ __launch_bounds__(256, 2) void vq_main(const float* __restrict__ z,
                                                  const float* __restrict__ cb,
                                                  float* __restrict__ out) {
    extern __shared__ char sm[];
    const uint32_t su = smem_u32(sm);
    const int t = threadIdx.x, w = t >> 5, lane = t & 31;
    const int g = lane >> 2, p = lane & 3;
    const int mw = w >> 1, nw = w & 1;
    const int n0 = blockIdx.x * 128;
    const int b = n0 >> 10, hw0 = n0 & 1023;
    const float* zb = z + b * (D * HW) + hw0;

    uint16_t* sA   = (uint16_t*)(sm + OFF_A);
    float*    scn  = (float*)(sm + OFF_CN);
    float4*   stg  = (float4*)(sm + OFF_STG);
    float*    sv3  = (float*)(sm + OFF_V3);
    int*      sRow = (int*)(sm + OFF_ROW);
    int*      sPT  = (int*)(sm + OFF_PT);
    int2*     sPC  = (int2*)(sm + OFF_PC);
    int*      sDP  = (int*)(sm + OFF_DP);
    int*      sCnt = (int*)(sm + OFF_CNT);
    unsigned long long* sBest = (unsigned long long*)(sm + OFF_CNT + 8);
    float*    wsum = (float*)(sm + OFF_CNT + 16);

    if (t == 0) { sCnt[0] = 0; sCnt[1] = 0; }

    // ---- A: load z coalesced -> fp16 smem [tok][dim] ----
#pragma unroll
    for (int j = 0; j < 32; j++) {
        int l = j * 256 + t;
        int d = l >> 5, f4 = l & 31;
        float4 v = *(const float4*)(zb + d * HW + f4 * 4);
        float vv[4] = {v.x, v.y, v.z, v.w};
#pragma unroll
        for (int q = 0; q < 4; q++)
            sA[(f4 * 4 + q) * 264 + d] = __half_as_ushort(__float2half(vv[q]));
    }
    for (int c = t; c < K; c += 256) scn[c] = g_cnorm[c];

#pragma unroll
    for (int j = 0; j < 4; j++) {
        int s = j * 256 + t;
        int code = s >> 5, seg = s & 31;
        CP_ASYNC16(su + OFF_B + code * 528 + seg * 16,
                   (const char*)g_cbf16 + code * 512 + seg * 16);
    }
    CP_COMMIT();
    __syncthreads();

    const int l8 = lane & 7, mat = lane >> 3;
    const uint32_t aAddr = su + OFF_A
        + (uint32_t)((mw * 32 + l8 + (mat & 1) * 8) * 528 + (mat >> 1) * 16);
    const uint32_t boff = (uint32_t)((nw * 16 + (mat >> 1) * 8 + l8) * 528 + (mat & 1) * 16);

    float rv1[2][2], rv2[2][2], rv3[2][2];
    int   ri1[2][2], ri2[2][2];
#pragma unroll
    for (int mt = 0; mt < 2; mt++)
#pragma unroll
        for (int rr = 0; rr < 2; rr++) {
            rv1[mt][rr] = 3.4e38f; rv2[mt][rr] = 3.4e38f; rv3[mt][rr] = 3.4e38f;
            ri1[mt][rr] = 0; ri2[mt][rr] = 0;
        }

    for (int nc = 0; nc < 32; nc++) {
        if (nc < 31) {
            int nn = nc + 1, buf = nn & 1;
#pragma unroll
            for (int j = 0; j < 4; j++) {
                int s = j * 256 + t;
                int code = s >> 5, seg = s & 31;
                CP_ASYNC16(su + OFF_B + buf * BBUF_SZ + code * 528 + seg * 16,
                           (const char*)g_cbf16 + (nn * 32 + code) * 512 + seg * 16);
            }
            CP_COMMIT();
            CP_WAIT1();
        } else {
            CP_WAIT0();
        }
        __syncthreads();

        const uint32_t bAddr = su + OFF_B + (uint32_t)(nc & 1) * BBUF_SZ + boff;

        float acc[2][2][4];
#pragma unroll
        for (int mt = 0; mt < 2; mt++)
#pragma unroll
            for (int nt = 0; nt < 2; nt++)
#pragma unroll
                for (int q = 0; q < 4; q++) acc[mt][nt][q] = 0.f;

        uint32_t ah[2][2][4], bb[2][4];
        ldsm_x4(ah[0][0], aAddr);
        ldsm_x4(ah[0][1], aAddr + 16 * 528);
        ldsm_x4(bb[0], bAddr);

#pragma unroll
        for (int ks = 0; ks < 16; ks++) {
            const int cur = ks & 1, nxt = cur ^ 1;
            if (ks < 15) {
                uint32_t ko = (uint32_t)((ks + 1) * 32);
                ldsm_x4(ah[nxt][0], aAddr + ko);
                ldsm_x4(ah[nxt][1], aAddr + 16 * 528 + ko);
                ldsm_x4(bb[nxt], bAddr + ko);
            }
#pragma unroll
            for (int mt = 0; mt < 2; mt++)
#pragma unroll
                for (int nt = 0; nt < 2; nt++)
                    mma_fp16(acc[mt][nt], ah[cur][mt], &bb[cur][nt * 2]);
        }

        // branchless fold into running top-(2+v3); codes ascending per thread
#pragma unroll
        for (int nt = 0; nt < 2; nt++)
#pragma unroll
            for (int q = 0; q < 2; q++) {
                int c = nc * 32 + nw * 16 + nt * 8 + 2 * p + q;
                float cn = scn[c];
#pragma unroll
                for (int mt = 0; mt < 2; mt++)
#pragma unroll
                    for (int rr = 0; rr < 2; rr++) {
                        float v = fmaf(-2.f, acc[mt][nt][rr * 2 + q], cn);
                        ins2v3(v, c, rv1[mt][rr], ri1[mt][rr],
                               rv2[mt][rr], ri2[mt][rr], rv3[mt][rr]);
                    }
            }
        __syncthreads();
    }

    // ---- merge across p lanes (xor 1, 2) ----
#pragma unroll
    for (int o = 1; o <= 2; o <<= 1) {
#pragma unroll
        for (int mt = 0; mt < 2; mt++)
#pragma unroll
            for (int rr = 0; rr < 2; rr++) {
                float ov1 = __shfl_xor_sync(~0u, rv1[mt][rr], o);
                int   oi1 = __shfl_xor_sync(~0u, ri1[mt][rr], o);
                float ov2 = __shfl_xor_sync(~0u, rv2[mt][rr], o);
                int   oi2 = __shfl_xor_sync(~0u, ri2[mt][rr], o);
                float ov3 = __shfl_xor_sync(~0u, rv3[mt][rr], o);
                ins2v3(ov1, oi1, rv1[mt][rr], ri1[mt][rr],
                       rv2[mt][rr], ri2[mt][rr], rv3[mt][rr]);
                ins2v3(ov2, oi2, rv1[mt][rr], ri1[mt][rr],
                       rv2[mt][rr], ri2[mt][rr], rv3[mt][rr]);
                rv3[mt][rr] = fminf(rv3[mt][rr], ov3);
            }
    }
    if (p == 0) {
#pragma unroll
        for (int mt = 0; mt < 2; mt++)
#pragma unroll
            for (int rr = 0; rr < 2; rr++) {
                int tok = mw * 32 + mt * 16 + rr * 8 + g;
                stg[tok * 2 + nw] = make_float4(rv1[mt][rr], __int_as_float(ri1[mt][rr]),
                                                rv2[mt][rr], __int_as_float(ri2[mt][rr]));
                sv3[tok * 2 + nw] = rv3[mt][rr];
            }
    }
    __syncthreads();

    // ---- per-token final merge + flag ----
    if (t < 128) {
        float4 a0 = stg[t * 2 + 0];
        float4 b0 = stg[t * 2 + 1];
        float fv1 = a0.x, fv2 = a0.z, fv3 = sv3[t * 2 + 0];
        int   fi1 = __float_as_int(a0.y), fi2 = __float_as_int(a0.w);
        ins2v3(b0.x, __float_as_int(b0.y), fv1, fi1, fv2, fi2, fv3);
        ins2v3(b0.z, __float_as_int(b0.w), fv1, fi1, fv2, fi2, fv3);
        fv3 = fminf(fv3, sv3[t * 2 + 1]);
        sRow[t] = fi1;
        if (fv3 - fv1 < MARGIN) {
            int s = atomicAdd(&sCnt[1], 1);
            sDP[s] = t;
        } else if (fv2 - fv1 < MARGIN) {
            int s = atomicAdd(&sCnt[0], 1);
            sPT[s] = t;
            sPC[s] = make_int2(fi1, fi2);
        }
    }
    __syncthreads();

    // ---- in-block exact fp32 pair rescore (one warp per flagged token) ----
    const int pairCnt = sCnt[0], deepCnt = sCnt[1];
    for (int i = w; i < pairCnt; i += 8) {
        int tok = sPT[i]; int2 cc = sPC[i];
        const float* zp = zb + tok;
        const float* p1 = cb + cc.x * D;
        const float* p2 = cb + cc.y * D;
        float zz = 0.f, d1 = 0.f, d2 = 0.f;
#pragma unroll
        for (int d = lane; d < D; d += 32) {
            float ze = zp[d * HW];
            zz = fmaf(ze, ze, zz);
            d1 = fmaf(ze, __ldg(p1 + d), d1);
            d2 = fmaf(ze, __ldg(p2 + d), d2);
        }
#pragma unroll
        for (int o = 16; o; o >>= 1) {
            zz += __shfl_xor_sync(~0u, zz, o);
            d1 += __shfl_xor_sync(~0u, d1, o);
            d2 += __shfl_xor_sync(~0u, d2, o);
        }
        if (lane == 0) {
            float D1 = __fadd_rn(__fsub_rn(zz, __fmul_rn(2.f, d1)), g_cnorm[cc.x]);
            float D2 = __fadd_rn(__fsub_rn(zz, __fmul_rn(2.f, d2)), g_cnorm[cc.y]);
            sRow[tok] = better(D2, cc.y, D1, cc.x) ? cc.y : cc.x;
        }
    }
    __syncthreads();

    // ---- in-block exact fp32 full scan for deep-doubt (rare) ----
    float* sz = (float*)(sm + OFF_B);
    for (int e = 0; e < deepCnt; e++) {
        int tok = sDP[e];
        sz[t] = zb[tok + t * HW];
        if (t == 0) *sBest = ~0ull;
        __syncthreads();
        const float4* szp = (const float4*)sz;
        float bv = 3.4e38f; int bi = 0;
#pragma unroll
        for (int j = 0; j < 4; j++) {
            int c = t + j * 256;
            const float4* row = (const float4*)(cb + c * D);
            float dsum = 0.f;
#pragma unroll 8
            for (int q = 0; q < 64; q++) {
                float4 zv = szp[q];
                float4 rv = __ldg(row + q);
                dsum = fmaf(zv.x, rv.x, dsum);
                dsum = fmaf(zv.y, rv.y, dsum);
                dsum = fmaf(zv.z, rv.z, dsum);
                dsum = fmaf(zv.w, rv.w, dsum);
            }
            float v = fmaf(-2.f, dsum, g_cnorm[c]);
            if (v < bv) { bv = v; bi = c; }
        }
        unsigned long long key = ((unsigned long long)fkey(bv) << 32) | (uint32_t)bi;
        atomicMin(sBest, key);
        __syncthreads();
        if (t == 0) sRow[tok] = (int)(*sBest & 0xffffffffu);
        __syncthreads();
    }

    // ---- outputs: indices, z_q_st, loss partial ----
    if (t < 128) out[IDX_OFF + n0 + t] = (float)sRow[t];
    float* outz = out + b * (D * HW) + hw0;
    float lsum = 0.f;
#pragma unroll 4
    for (int j = 0; j < 128; j++) {
        int l = j * 256 + t;
        int i = l & 127, d = l >> 7;
        float ze = zb[d * HW + i];
        float zq = __ldg(cb + sRow[i] * D + d);
        float diff = zq - ze;
        outz[d * HW + i] = ze + diff;
        lsum = fmaf(diff, diff, lsum);
    }
#pragma unroll
    for (int o = 16; o; o >>= 1) lsum += __shfl_xor_sync(~0u, lsum, o);
    if (lane == 0) wsum[w] = lsum;
    __syncthreads();
    if (t == 0) {
        float s = 0.f;
#pragma unroll
        for (int ww = 0; ww < 8; ww++) s += wsum[ww];
        g_partial[blockIdx.x] = s;
    }
}

// ---------------- Kernel 2: final loss ----------------
__global__ void finalize_kernel(float* __restrict__ out) {
    float s = 0.f;
    for (int i = 0; i < NBLK; i++) s += g_partial[i];
    float mean = s / 8388608.f;
    out[LOSS_OFF] = mean + 0.25f * mean;
}

// ---------------------------------------------------------------------------
extern "C" void kernel_launch(void* const* d_in, const int* in_sizes, int n_in,
                              void* d_out, int out_size) {
    const float* z  = (const float*)d_in[0];
    const float* cb = (const float*)d_in[1];
    float* out = (float*)d_out;

    cudaFuncSetAttribute(vq_main, cudaFuncAttributeMaxDynamicSharedMemorySize, SMEM_SZ);

    prepcn_kernel<<<K, 256>>>(cb);
    vq_main<<<NBLK, 256, SMEM_SZ>>>(z, cb, out);
    finalize_kernel<<<1, 1>>>(out);
}

// round 12
// speedup vs baseline: 2.7956x; 1.1973x over previous
#include <cuda_runtime.h>
#include <cuda_fp16.h>
#include <cstdint>

#define D        256
#define K        1024
#define HW       1024
#define NBLK     256
#define IDX_OFF  8388608
#define LOSS_OFF 8421376
#define MARGIN   0.12f

// smem layout (bytes)
#define OFF_A    0          // 128 x 264 halves = 67584 ; reused as output stage [32][260] f32
#define OFF_B    67584      // 2 bufs x 16896 (32 codes x 528B); reused as sz for deep scan
#define BBUF_SZ  16896
#define OFF_CN   101376     // 4096
#define OFF_STG  105472     // 256 x float4 = 4096
#define OFF_V3   109568     // 256 x float = 1024
#define OFF_ROW  110592     // 128 x int = 512
#define OFF_PT   111104     // pair tok, 128 x int
#define OFF_PC   111616     // pair codes, 128 x int2 = 1024
#define OFF_DP   112640     // deep tok, 128 x int
#define OFF_CNT  113152     // [0] pairCnt, [1] deepCnt; sbest @ +8; wsum @ +16
#define SMEM_SZ  113280

__device__ float    g_cnorm[K];
__device__ float    g_partial[NBLK];
__device__ uint16_t g_cbf16[K * D];

// ---------------- helpers ----------------
__device__ __forceinline__ uint32_t smem_u32(const void* p) {
    uint32_t a;
    asm("{ .reg .u64 t; cvta.to.shared.u64 t, %1; cvt.u32.u64 %0, t; }" : "=r"(a) : "l"(p));
    return a;
}
#define CP_ASYNC16(dst, src) \
    asm volatile("cp.async.cg.shared.global [%0], [%1], 16;" :: "r"(dst), "l"(src) : "memory")
#define CP_COMMIT() asm volatile("cp.async.commit_group;" ::: "memory")
#define CP_WAIT1()  asm volatile("cp.async.wait_group 1;" ::: "memory")
#define CP_WAIT0()  asm volatile("cp.async.wait_group 0;" ::: "memory")

__device__ __forceinline__ void ldsm_x4(uint32_t* r, uint32_t a) {
    asm volatile("ldmatrix.sync.aligned.m8n8.x4.shared.b16 {%0,%1,%2,%3}, [%4];"
        : "=r"(r[0]), "=r"(r[1]), "=r"(r[2]), "=r"(r[3]) : "r"(a));
}
__device__ __forceinline__ void mma_fp16(float* c, const uint32_t* a, const uint32_t* b) {
    asm volatile(
        "mma.sync.aligned.m16n8k16.row.col.f32.f16.f16.f32 "
        "{%0,%1,%2,%3}, {%4,%5,%6,%7}, {%8,%9}, {%0,%1,%2,%3};"
        : "+f"(c[0]), "+f"(c[1]), "+f"(c[2]), "+f"(c[3])
        : "r"(a[0]), "r"(a[1]), "r"(a[2]), "r"(a[3]), "r"(b[0]), "r"(b[1]));
}
// exact tie rule (used only in rescue paths)
__device__ __forceinline__ bool better(float v, int i, float V, int I) {
    return v < V || (v == V && i < I);
}
// strict-< branchless insert; ties fall out as gap==0 -> flagged -> exact rescue
__device__ __forceinline__ void ins2v3(float v, int i,
                                       float& v1, int& i1, float& v2, int& i2, float& v3) {
    bool lt2 = v < v2;
    bool lt1 = v < v1;
    v3 = lt2 ? v2 : fminf(v3, v);
    float nv2 = lt1 ? v1 : v;  int ni2 = lt1 ? i1 : i;
    v2 = lt2 ? nv2 : v2;       i2 = lt2 ? ni2 : i2;
    v1 = lt1 ? v : v1;         i1 = lt1 ? i : i1;
}
__device__ __forceinline__ uint32_t fkey(float f) {
    uint32_t u = __float_as_uint(f);
    return (u & 0x80000000u) ? ~u : (u | 0x80000000u);
}

// ---------------- Kernel 0: codebook -> fp16 + cnorm (fused) ----------------
__global__ __launch_bounds__(256) void prepcn_kernel(const float* __restrict__ cb) {
    __shared__ float ws[8];
    const int r = blockIdx.x, t = threadIdx.x;
    float v = cb[r * D + t];
    g_cbf16[r * D + t] = __half_as_ushort(__float2half(v));
    float s = v * v;
#pragma unroll
    for (int o = 16; o; o >>= 1) s += __shfl_xor_sync(~0u, s, o);
    if ((t & 31) == 0) ws[t >> 5] = s;
    __syncthreads();
    if (t == 0) {
        float tot = 0.f;
#pragma unroll
        for (int i = 0; i < 8; i++) tot += ws[i];
        g_cnorm[r] = tot;
    }
}

// ---------------- Kernel 1: fused GEMM + argmin + rescue + outputs ----------------
__global__ __launch_bounds__(256, 2) void vq_main(const float* __restrict__ z,
                                                  const float* __restrict__ cb,
                                                  float* __restrict__ out) {
    extern __shared__ char sm[];
    const uint32_t su = smem_u32(sm);
    const int t = threadIdx.x, w = t >> 5, lane = t & 31;
    const int g = lane >> 2, p = lane & 3;
    const int mw = w >> 1, nw = w & 1;
    const int n0 = blockIdx.x * 128;
    const int b = n0 >> 10, hw0 = n0 & 1023;
    const float* zb = z + b * (D * HW) + hw0;

    uint16_t* sA   = (uint16_t*)(sm + OFF_A);
    float*    scn  = (float*)(sm + OFF_CN);
    float4*   stg  = (float4*)(sm + OFF_STG);
    float*    sv3  = (float*)(sm + OFF_V3);
    int*      sRow = (int*)(sm + OFF_ROW);
    int*      sPT  = (int*)(sm + OFF_PT);
    int2*     sPC  = (int2*)(sm + OFF_PC);
    int*      sDP  = (int*)(sm + OFF_DP);
    int*      sCnt = (int*)(sm + OFF_CNT);
    unsigned long long* sBest = (unsigned long long*)(sm + OFF_CNT + 8);
    float*    wsum = (float*)(sm + OFF_CNT + 16);

    if (t == 0) { sCnt[0] = 0; sCnt[1] = 0; }

    // ---- A: load z coalesced -> fp16 smem [tok][dim] ----
#pragma unroll
    for (int j = 0; j < 32; j++) {
        int l = j * 256 + t;
        int d = l >> 5, f4 = l & 31;
        float4 v = *(const float4*)(zb + d * HW + f4 * 4);
        float vv[4] = {v.x, v.y, v.z, v.w};
#pragma unroll
        for (int q = 0; q < 4; q++)
            sA[(f4 * 4 + q) * 264 + d] = __half_as_ushort(__float2half(vv[q]));
    }
    for (int c = t; c < K; c += 256) scn[c] = g_cnorm[c];

#pragma unroll
    for (int j = 0; j < 4; j++) {
        int s = j * 256 + t;
        int code = s >> 5, seg = s & 31;
        CP_ASYNC16(su + OFF_B + code * 528 + seg * 16,
                   (const char*)g_cbf16 + code * 512 + seg * 16);
    }
    CP_COMMIT();
    __syncthreads();

    const int l8 = lane & 7, mat = lane >> 3;
    const uint32_t aAddr = su + OFF_A
        + (uint32_t)((mw * 32 + l8 + (mat & 1) * 8) * 528 + (mat >> 1) * 16);
    const uint32_t boff = (uint32_t)((nw * 16 + (mat >> 1) * 8 + l8) * 528 + (mat & 1) * 16);

    float rv1[2][2], rv2[2][2], rv3[2][2];
    int   ri1[2][2], ri2[2][2];
#pragma unroll
    for (int mt = 0; mt < 2; mt++)
#pragma unroll
        for (int rr = 0; rr < 2; rr++) {
            rv1[mt][rr] = 3.4e38f; rv2[mt][rr] = 3.4e38f; rv3[mt][rr] = 3.4e38f;
            ri1[mt][rr] = 0; ri2[mt][rr] = 0;
        }

    for (int nc = 0; nc < 32; nc++) {
        if (nc < 31) {
            int nn = nc + 1, buf = nn & 1;
#pragma unroll
            for (int j = 0; j < 4; j++) {
                int s = j * 256 + t;
                int code = s >> 5, seg = s & 31;
                CP_ASYNC16(su + OFF_B + buf * BBUF_SZ + code * 528 + seg * 16,
                           (const char*)g_cbf16 + (nn * 32 + code) * 512 + seg * 16);
            }
            CP_COMMIT();
            CP_WAIT1();
        } else {
            CP_WAIT0();
        }
        __syncthreads();

        const uint32_t bAddr = su + OFF_B + (uint32_t)(nc & 1) * BBUF_SZ + boff;

        float acc[2][2][4];
#pragma unroll
        for (int mt = 0; mt < 2; mt++)
#pragma unroll
            for (int nt = 0; nt < 2; nt++)
#pragma unroll
                for (int q = 0; q < 4; q++) acc[mt][nt][q] = 0.f;

        uint32_t ah[2][2][4], bb[2][4];
        ldsm_x4(ah[0][0], aAddr);
        ldsm_x4(ah[0][1], aAddr + 16 * 528);
        ldsm_x4(bb[0], bAddr);

#pragma unroll
        for (int ks = 0; ks < 16; ks++) {
            const int cur = ks & 1, nxt = cur ^ 1;
            if (ks < 15) {
                uint32_t ko = (uint32_t)((ks + 1) * 32);
                ldsm_x4(ah[nxt][0], aAddr + ko);
                ldsm_x4(ah[nxt][1], aAddr + 16 * 528 + ko);
                ldsm_x4(bb[nxt], bAddr + ko);
            }
#pragma unroll
            for (int mt = 0; mt < 2; mt++)
#pragma unroll
                for (int nt = 0; nt < 2; nt++)
                    mma_fp16(acc[mt][nt], ah[cur][mt], &bb[cur][nt * 2]);
        }

        // strict-< branchless fold; codes ascending per thread
#pragma unroll
        for (int nt = 0; nt < 2; nt++)
#pragma unroll
            for (int q = 0; q < 2; q++) {
                int c = nc * 32 + nw * 16 + nt * 8 + 2 * p + q;
                float cn = scn[c];
#pragma unroll
                for (int mt = 0; mt < 2; mt++)
#pragma unroll
                    for (int rr = 0; rr < 2; rr++) {
                        float v = fmaf(-2.f, acc[mt][nt][rr * 2 + q], cn);
                        ins2v3(v, c, rv1[mt][rr], ri1[mt][rr],
                               rv2[mt][rr], ri2[mt][rr], rv3[mt][rr]);
                    }
            }
        __syncthreads();
    }

    // ---- merge across p lanes (xor 1, 2) ----
#pragma unroll
    for (int o = 1; o <= 2; o <<= 1) {
#pragma unroll
        for (int mt = 0; mt < 2; mt++)
#pragma unroll
            for (int rr = 0; rr < 2; rr++) {
                float ov1 = __shfl_xor_sync(~0u, rv1[mt][rr], o);
                int   oi1 = __shfl_xor_sync(~0u, ri1[mt][rr], o);
                float ov2 = __shfl_xor_sync(~0u, rv2[mt][rr], o);
                int   oi2 = __shfl_xor_sync(~0u, ri2[mt][rr], o);
                float ov3 = __shfl_xor_sync(~0u, rv3[mt][rr], o);
                ins2v3(ov1, oi1, rv1[mt][rr], ri1[mt][rr],
                       rv2[mt][rr], ri2[mt][rr], rv3[mt][rr]);
                ins2v3(ov2, oi2, rv1[mt][rr], ri1[mt][rr],
                       rv2[mt][rr], ri2[mt][rr], rv3[mt][rr]);
                rv3[mt][rr] = fminf(rv3[mt][rr], ov3);
            }
    }
    if (p == 0) {
#pragma unroll
        for (int mt = 0; mt < 2; mt++)
#pragma unroll
            for (int rr = 0; rr < 2; rr++) {
                int tok = mw * 32 + mt * 16 + rr * 8 + g;
                stg[tok * 2 + nw] = make_float4(rv1[mt][rr], __int_as_float(ri1[mt][rr]),
                                                rv2[mt][rr], __int_as_float(ri2[mt][rr]));
                sv3[tok * 2 + nw] = rv3[mt][rr];
            }
    }
    __syncthreads();

    // ---- per-token final merge + flag ----
    if (t < 128) {
        float4 a0 = stg[t * 2 + 0];
        float4 b0 = stg[t * 2 + 1];
        float fv1 = a0.x, fv2 = a0.z, fv3 = sv3[t * 2 + 0];
        int   fi1 = __float_as_int(a0.y), fi2 = __float_as_int(a0.w);
        ins2v3(b0.x, __float_as_int(b0.y), fv1, fi1, fv2, fi2, fv3);
        ins2v3(b0.z, __float_as_int(b0.w), fv1, fi1, fv2, fi2, fv3);
        fv3 = fminf(fv3, sv3[t * 2 + 1]);
        sRow[t] = fi1;
        if (fv3 - fv1 < MARGIN) {
            int s = atomicAdd(&sCnt[1], 1);
            sDP[s] = t;
        } else if (fv2 - fv1 < MARGIN) {
            int s = atomicAdd(&sCnt[0], 1);
            sPT[s] = t;
            sPC[s] = make_int2(fi1, fi2);
        }
    }
    __syncthreads();

    // ---- in-block exact fp32 pair rescore (one warp per flagged token) ----
    const int pairCnt = sCnt[0], deepCnt = sCnt[1];
    for (int i = w; i < pairCnt; i += 8) {
        int tok = sPT[i]; int2 cc = sPC[i];
        const float* zp = zb + tok;
        const float* p1 = cb + cc.x * D;
        const float* p2 = cb + cc.y * D;
        float zz = 0.f, d1 = 0.f, d2 = 0.f;
#pragma unroll
        for (int d = lane; d < D; d += 32) {
            float ze = zp[d * HW];
            zz = fmaf(ze, ze, zz);
            d1 = fmaf(ze, __ldg(p1 + d), d1);
            d2 = fmaf(ze, __ldg(p2 + d), d2);
        }
#pragma unroll
        for (int o = 16; o; o >>= 1) {
            zz += __shfl_xor_sync(~0u, zz, o);
            d1 += __shfl_xor_sync(~0u, d1, o);
            d2 += __shfl_xor_sync(~0u, d2, o);
        }
        if (lane == 0) {
            float D1 = __fadd_rn(__fsub_rn(zz, __fmul_rn(2.f, d1)), g_cnorm[cc.x]);
            float D2 = __fadd_rn(__fsub_rn(zz, __fmul_rn(2.f, d2)), g_cnorm[cc.y]);
            sRow[tok] = better(D2, cc.y, D1, cc.x) ? cc.y : cc.x;
        }
    }
    __syncthreads();

    // ---- in-block exact fp32 full scan for deep-doubt (rare) ----
    float* sz = (float*)(sm + OFF_B);
    for (int e = 0; e < deepCnt; e++) {
        int tok = sDP[e];
        sz[t] = zb[tok + t * HW];
        if (t == 0) *sBest = ~0ull;
        __syncthreads();
        const float4* szp = (const float4*)sz;
        float bv = 3.4e38f; int bi = 0;
#pragma unroll
        for (int j = 0; j < 4; j++) {
            int c = t + j * 256;
            const float4* row = (const float4*)(cb + c * D);
            float dsum = 0.f;
#pragma unroll 8
            for (int q = 0; q < 64; q++) {
                float4 zv = szp[q];
                float4 rv = __ldg(row + q);
                dsum = fmaf(zv.x, rv.x, dsum);
                dsum = fmaf(zv.y, rv.y, dsum);
                dsum = fmaf(zv.z, rv.z, dsum);
                dsum = fmaf(zv.w, rv.w, dsum);
            }
            float v = fmaf(-2.f, dsum, g_cnorm[c]);
            if (v < bv) { bv = v; bi = c; }
        }
        unsigned long long key = ((unsigned long long)fkey(bv) << 32) | (uint32_t)bi;
        atomicMin(sBest, key);
        __syncthreads();
        if (t == 0) sRow[tok] = (int)(*sBest & 0xffffffffu);
        __syncthreads();
    }

    // ---- outputs: indices, z_q_st via smem-staged coalesced gather, loss ----
    if (t < 128) out[IDX_OFF + n0 + t] = (float)sRow[t];

    float* stage = (float*)(sm + OFF_A);   // [32][260] f32 (reuses A panel space)
    float* outz = out + b * (D * HW) + hw0;
    float lsum = 0.f;
    for (int g4 = 0; g4 < 4; g4++) {
        const int i0 = g4 * 32;
        __syncthreads();     // stage safe to overwrite
#pragma unroll
        for (int j = 0; j < 8; j++) {
            int idx = j * 256 + t;
            int tl = idx >> 6, f4 = idx & 63;
            float4 v = __ldg((const float4*)(cb + sRow[i0 + tl] * D) + f4);
            *(float4*)(stage + tl * 260 + f4 * 4) = v;
        }
        __syncthreads();
#pragma unroll 8
        for (int j = 0; j < 32; j++) {
            int l = j * 256 + t;
            int d = l >> 5, i = l & 31;
            float ze = zb[d * HW + i0 + i];
            float zq = stage[i * 260 + d];
            float diff = zq - ze;
            outz[d * HW + i0 + i] = ze + diff;
            lsum = fmaf(diff, diff, lsum);
        }
    }
#pragma unroll
    for (int o = 16; o; o >>= 1) lsum += __shfl_xor_sync(~0u, lsum, o);
    if (lane == 0) wsum[w] = lsum;
    __syncthreads();
    if (t == 0) {
        float s = 0.f;
#pragma unroll
        for (int ww = 0; ww < 8; ww++) s += wsum[ww];
        g_partial[blockIdx.x] = s;
    }
}

// ---------------- Kernel 2: final loss ----------------
__global__ void finalize_kernel(float* __restrict__ out) {
    float s = 0.f;
    for (int i = 0; i < NBLK; i++) s += g_partial[i];
    float mean = s / 8388608.f;
    out[LOSS_OFF] = mean + 0.25f * mean;
}

// ---------------------------------------------------------------------------
extern "C" void kernel_launch(void* const* d_in, const int* in_sizes, int n_in,
                              void* d_out, int out_size) {
    const float* z  = (const float*)d_in[0];
    const float* cb = (const float*)d_in[1];
    float* out = (float*)d_out;

    cudaFuncSetAttribute(vq_main, cudaFuncAttributeMaxDynamicSharedMemorySize, SMEM_SZ);

    prepcn_kernel<<<K, 256>>>(cb);
    vq_main<<<NBLK, 256, SMEM_SZ>>>(z, cb, out);
    finalize_kernel<<<1, 1>>>(out);
}